// round 15
// baseline (speedup 1.0000x reference)
#include <cuda_runtime.h>
#include <cuda_fp16.h>
#include <cstdint>

#define EMBED   1024
#define NHEADS  16
#define HDIM    64
#define BATCH   2
#define SEQ     2048
#define MROWS   (BATCH*SEQ)   // 4096

#define NEG_INF (-1e30f)

typedef __half fh;

// tcgen05 is NOT usable (harness emits compute_103 PTX; ptxas rejects it).
// All tensor work via mma.sync HMMA, fp16 operands + fp32 accumulators.
// rel_err ~5.2e-4 vs 1e-3 threshold — do not cut precision further.

// ---------------------------------------------------------------------------
// Scratch (device globals). Everything single fp16.
// ---------------------------------------------------------------------------
__device__ fh g_X[(size_t)MROWS*EMBED];
__device__ fh g_Wq[(size_t)3*EMBED*EMBED];
__device__ fh g_Wo[(size_t)EMBED*EMBED];
__device__ fh g_Q[(size_t)MROWS*EMBED];
__device__ fh g_K[(size_t)MROWS*EMBED];
__device__ fh g_V[(size_t)MROWS*EMBED];
__device__ fh g_C[(size_t)MROWS*EMBED];

// ---------------------------------------------------------------------------
// PTX helpers
// ---------------------------------------------------------------------------
__device__ __forceinline__ uint32_t saddr(const void* p) {
    return (uint32_t)__cvta_generic_to_shared(p);
}
__device__ __forceinline__ void cpa16(uint32_t dst, const void* src) {
    asm volatile("cp.async.cg.shared.global [%0], [%1], 16;\n" :: "r"(dst), "l"(src));
}
__device__ __forceinline__ void cpa_commit() {
    asm volatile("cp.async.commit_group;\n");
}
template<int N>
__device__ __forceinline__ void cpa_wait() {
    asm volatile("cp.async.wait_group %0;\n" :: "n"(N));
}
__device__ __forceinline__ void ldsm_x4(uint32_t& r0, uint32_t& r1,
                                        uint32_t& r2, uint32_t& r3, uint32_t a) {
    asm volatile("ldmatrix.sync.aligned.m8n8.x4.shared.b16 {%0,%1,%2,%3}, [%4];"
                 : "=r"(r0), "=r"(r1), "=r"(r2), "=r"(r3) : "r"(a));
}
__device__ __forceinline__ void ldsm_x4_t(uint32_t& r0, uint32_t& r1,
                                          uint32_t& r2, uint32_t& r3, uint32_t a) {
    asm volatile("ldmatrix.sync.aligned.m8n8.x4.trans.shared.b16 {%0,%1,%2,%3}, [%4];"
                 : "=r"(r0), "=r"(r1), "=r"(r2), "=r"(r3) : "r"(a));
}
__device__ __forceinline__ void mma_f16(float* c, const uint32_t* a, const uint32_t* b) {
    asm volatile(
        "mma.sync.aligned.m16n8k16.row.col.f32.f16.f16.f32 "
        "{%0,%1,%2,%3}, {%4,%5,%6,%7}, {%8,%9}, {%0,%1,%2,%3};"
        : "+f"(c[0]), "+f"(c[1]), "+f"(c[2]), "+f"(c[3])
        : "r"(a[0]), "r"(a[1]), "r"(a[2]), "r"(a[3]), "r"(b[0]), "r"(b[1]));
}
__device__ __forceinline__ uint32_t packh2(float a, float b) {
    __half2 h = __floats2half2_rn(a, b);   // a -> low half
    return *(uint32_t*)&h;
}

// ---------------------------------------------------------------------------
// Input conversion pre-pass: x, w_qkv, w_out -> fp16 globals.
// ---------------------------------------------------------------------------
__global__ __launch_bounds__(256)
void cvt_inputs(const float* __restrict__ x, const float* __restrict__ wq,
                const float* __restrict__ wo)
{
    const int i = blockIdx.x * 256 + threadIdx.x;
    const float* src; fh* dst; int off;
    if (i < 1048576)            { src = x;  dst = g_X;  off = i; }
    else if (i < 1048576+786432){ src = wq; dst = g_Wq; off = i - 1048576; }
    else                        { src = wo; dst = g_Wo; off = i - 1835008; }
    float4 f = ((const float4*)src)[off];
    uint2 v; v.x = packh2(f.x, f.y); v.y = packh2(f.z, f.w);
    *(uint2*)(dst + (size_t)off*4) = v;
}

// ---------------------------------------------------------------------------
// Pipelined fp16 HMMA GEMM: out = A @ Bw^T + bias
// 256 threads, CTA tile 128x128, 8 warps (2m x 4n), warp tile 64x32.
// NEW: K-step 64 (was 32) — halves per-iteration sync/wait fixed costs,
// which dominate now that fp16-single carries 3x fewer MMAs per step.
// Rows 64 halves + 8 pad = 144 B (bank-conflict-free, proven in attn).
// 2-stage cp.async, 2 CTAs/SM. Stage: A 18432 B + B 18432 B = 36864 B.
// ---------------------------------------------------------------------------
#define GSTAGE_B  36864
#define GEMM_SMEM (2*GSTAGE_B)   // 73728

template<int MODE>
__global__ __launch_bounds__(256, 2)
void gemm_h(const float* __restrict__ bias, float* __restrict__ C,
            int M, int N, int K)
{
    extern __shared__ fh sm[];
    const uint32_t smem0 = saddr(sm);

    const fh* Ap = (MODE == 0) ? g_X : g_C;
    const fh* Bp = (MODE == 0) ? g_Wq : g_Wo;

    const int tid  = threadIdx.x;
    const int lane = tid & 31;
    const int warp = tid >> 5;
    const int wm   = warp >> 2;
    const int wn   = warp & 3;
    const int bm   = blockIdx.y * 128;
    const int bn   = blockIdx.x * 128;

    const int lr    = tid >> 1;          // 0..127 tile row
    const int half_ = tid & 1;           // which 32-half chunk of the 64-half row

    const fh* aP = Ap + (size_t)(bm + lr) * K + half_*32;
    const fh* bP = Bp + (size_t)(bn + lr) * K + half_*32;
    const uint32_t adst = smem0 + lr*144 + half_*64;
    const uint32_t bdst = adst + 18432;

    const int nsteps = K >> 6;           // K-step 64

    auto copy_stage = [&](int k0, int stg) {
        const uint32_t d = stg * GSTAGE_B;
        #pragma unroll
        for (int j = 0; j < 4; j++) {
            cpa16(adst + d + j*16, aP + k0 + j*8);
            cpa16(bdst + d + j*16, bP + k0 + j*8);
        }
    };

    float acc[16][4];
    #pragma unroll
    for (int i = 0; i < 16; i++)
        #pragma unroll
        for (int j = 0; j < 4; j++) acc[i][j] = 0.f;

    const int arow = wm*64 + (lane & 15);
    const int acol = ((lane >> 4) & 1) * 8;
    const int brow = wn*32 + (lane & 7) + ((lane >> 4) & 1) * 8;
    const int bcol = ((lane >> 3) & 1) * 8;
    const uint32_t aoff = (uint32_t)(arow*144 + acol*2);
    const uint32_t boff = (uint32_t)(18432 + brow*144 + bcol*2);

    copy_stage(0, 0);  cpa_commit();

    for (int ks = 0; ks < nsteps; ks++) {
        const int nk = ks + 1;
        if (nk < nsteps) copy_stage(nk*64, nk & 1);
        cpa_commit();
        cpa_wait<1>();
        __syncthreads();

        const uint32_t base = smem0 + (ks & 1) * GSTAGE_B;

        #pragma unroll
        for (int kk = 0; kk < 4; kk++) {
            const uint32_t ab  = base + aoff + kk*32;
            const uint32_t bbx = base + boff + kk*32;
            uint32_t bh[2][4];
            #pragma unroll
            for (int p = 0; p < 2; p++)
                ldsm_x4(bh[p][0], bh[p][1], bh[p][2], bh[p][3], bbx + p*2304);
            #pragma unroll
            for (int t = 0; t < 4; t++) {
                uint32_t ah[4];
                ldsm_x4(ah[0], ah[1], ah[2], ah[3], ab + t*2304);
                #pragma unroll
                for (int n = 0; n < 4; n++)
                    mma_f16(acc[t*4 + n], ah, &bh[n >> 1][(n & 1) * 2]);
            }
        }
        __syncthreads();
    }

    // epilogue
    #pragma unroll
    for (int t = 0; t < 4; t++) {
        const int r0 = bm + wm*64 + t*16 + (lane >> 2);
        #pragma unroll
        for (int n = 0; n < 4; n++) {
            const int col = bn + wn*32 + n*8 + (lane & 3)*2;
            const float b0v = bias[col], b1v = bias[col + 1];
            const float* c = acc[t*4 + n];
            if (MODE == 0) {
                const int sel = col >> 10;      // 0=Q 1=K 2=V
                const int e   = col & 1023;
                fh* pq = (sel == 0) ? g_Q : (sel == 1) ? g_K : g_V;
                const int hh = e >> 6, dd = e & 63;
                #pragma unroll
                for (int rr = 0; rr < 2; rr++) {
                    const int row = r0 + rr*8;
                    const int bbv = row >> 11, ss = row & 2047;
                    const size_t idx = (((size_t)(bbv*NHEADS + hh))*SEQ + ss)*HDIM + dd;
                    *(uint32_t*)&pq[idx] = packh2(c[rr*2] + b0v, c[rr*2+1] + b1v);
                }
            } else {
                float2 v0; v0.x = c[0] + b0v; v0.y = c[1] + b1v;
                float2 v1; v1.x = c[2] + b0v; v1.y = c[3] + b1v;
                *(float2*)&C[(size_t)r0       * N + col] = v0;
                *(float2*)&C[(size_t)(r0 + 8) * N + col] = v1;
            }
        }
    }
}

// ---------------------------------------------------------------------------
// fp16 flash attention (causal), fp32 accumulators.
// 2-stage double-buffered K/V cp.async pipeline (unchanged — proven 264us).
// smem (halves): Q[128][72] @0, K stages @9216+stg*4608, V @18432+stg*4608.
// ---------------------------------------------------------------------------
#define ATTN_SMEM_BYTES 55296

__global__ __launch_bounds__(256, 1)
void attn_h()
{
    extern __shared__ fh sb[];
    fh (*Qs)[72] = (fh(*)[72])(sb);

    const int qt   = (int)(gridDim.x - 1) - (int)blockIdx.x;   // big tiles first
    const int bhid = blockIdx.y;
    const int bb   = bhid / NHEADS;
    const int hh   = bhid % NHEADS;

    const size_t hb = (size_t)bhid * SEQ * HDIM;

    const int tid  = threadIdx.x;
    const int lane = tid & 31;
    const int w    = tid >> 5;
    const int qbase = qt * 128;

    const int kr = tid >> 2, q4 = tid & 3;

    auto load_kv = [&](int kt, int stg) {
        const size_t srcoff = hb + (size_t)(kt*64 + kr)*HDIM + q4*16;
        const uint32_t doff = (uint32_t)(stg*9216 + kr*144 + q4*32);
        const uint32_t dk = saddr(sb + 9216)  + doff;
        const uint32_t dv = saddr(sb + 18432) + doff;
        cpa16(dk, g_K + srcoff);  cpa16(dk + 16, g_K + srcoff + 8);
        cpa16(dv, g_V + srcoff);  cpa16(dv + 16, g_V + srcoff + 8);
    };

    const int nktiles = 2*qt + 2;

    // prologue: load Q (group A), prefetch K/V tile 0 (group B)
    {
        const int lr = tid >> 1, hx = tid & 1;
        const fh* qsrc = g_Q + hb + (size_t)(qbase + lr)*HDIM + hx*32;
        const uint32_t dq = saddr(&Qs[lr][hx*32]);
        #pragma unroll
        for (int u = 0; u < 4; u++)
            cpa16(dq + u*16, qsrc + u*8);
        cpa_commit();                 // group A (Q)
    }
    load_kv(0, 0);
    cpa_commit();                     // group B (KV tile 0)
    cpa_wait<1>();                    // Q complete
    __syncthreads();

    uint32_t qf[4][4];
    {
        const int arow = w*16 + (lane & 15);
        const int acol = ((lane >> 4) & 1) * 8;
        #pragma unroll
        for (int kc = 0; kc < 4; kc++)
            ldsm_x4(qf[kc][0], qf[kc][1], qf[kc][2], qf[kc][3],
                    saddr(&Qs[arow][kc*16 + acol]));
    }

    float O[8][4];
    #pragma unroll
    for (int nt = 0; nt < 8; nt++)
        #pragma unroll
        for (int e = 0; e < 4; e++) O[nt][e] = 0.f;

    float m0 = NEG_INF, m1 = NEG_INF, l0 = 0.f, l1 = 0.f;
    const int r0g = qbase + w*16 + (lane >> 2);
    const int r1g = r0g + 8;
    const int wr  = qbase + w*16;

    const int krow = (lane & 7) + ((lane >> 4) & 1) * 8;
    const int kcol = ((lane >> 3) & 1) * 8;
    const int vrow = (lane & 7) + ((lane >> 3) & 1) * 8;
    const int vcol = ((lane >> 4) & 1) * 8;

    for (int kt = 0; kt < nktiles; kt++) {
        const int kbase = kt * 64;
        __syncthreads();   // all warps done reading the stage about to refill

        const int nk = kt + 1;
        if (nk < nktiles) load_kv(nk, nk & 1);
        cpa_commit();
        cpa_wait<1>();     // current tile complete; next may be in flight
        __syncthreads();

        if (wr + 15 < kbase) continue;

        const uint32_t kbs = saddr(sb + 9216)  + (kt & 1)*9216;
        const uint32_t vbs = saddr(sb + 18432) + (kt & 1)*9216;

        // S = Q K^T
        float s[8][4];
        #pragma unroll
        for (int nt = 0; nt < 8; nt++)
            #pragma unroll
            for (int e = 0; e < 4; e++) s[nt][e] = 0.f;

        #pragma unroll
        for (int kc = 0; kc < 4; kc++) {
            uint32_t k4[4][4];
            #pragma unroll
            for (int p = 0; p < 4; p++)
                ldsm_x4(k4[p][0], k4[p][1], k4[p][2], k4[p][3],
                        kbs + (uint32_t)((p*16 + krow)*144 + (kc*16 + kcol)*2));
            #pragma unroll
            for (int nt = 0; nt < 8; nt++)
                mma_f16(s[nt], qf[kc], &k4[nt >> 1][(nt & 1) * 2]);
        }

        #pragma unroll
        for (int nt = 0; nt < 8; nt++)
            #pragma unroll
            for (int e = 0; e < 4; e++) s[nt][e] *= 0.125f;

        if (kbase + 63 > wr) {
            #pragma unroll
            for (int nt = 0; nt < 8; nt++) {
                const int c0 = kbase + nt*8 + ((lane & 3) << 1);
                if (c0     > r0g) s[nt][0] = NEG_INF;
                if (c0 + 1 > r0g) s[nt][1] = NEG_INF;
                if (c0     > r1g) s[nt][2] = NEG_INF;
                if (c0 + 1 > r1g) s[nt][3] = NEG_INF;
            }
        }

        // online softmax
        float mx0 = NEG_INF, mx1 = NEG_INF;
        #pragma unroll
        for (int nt = 0; nt < 8; nt++) {
            mx0 = fmaxf(mx0, fmaxf(s[nt][0], s[nt][1]));
            mx1 = fmaxf(mx1, fmaxf(s[nt][2], s[nt][3]));
        }
        mx0 = fmaxf(mx0, __shfl_xor_sync(0xffffffffu, mx0, 1));
        mx0 = fmaxf(mx0, __shfl_xor_sync(0xffffffffu, mx0, 2));
        mx1 = fmaxf(mx1, __shfl_xor_sync(0xffffffffu, mx1, 1));
        mx1 = fmaxf(mx1, __shfl_xor_sync(0xffffffffu, mx1, 2));

        const float nm0 = fmaxf(m0, mx0);
        const float nm1 = fmaxf(m1, mx1);
        const float f0 = __expf(m0 - nm0);
        const float f1 = __expf(m1 - nm1);

        float ps0 = 0.f, ps1 = 0.f;
        #pragma unroll
        for (int nt = 0; nt < 8; nt++) {
            s[nt][0] = __expf(s[nt][0] - nm0);
            s[nt][1] = __expf(s[nt][1] - nm0);
            s[nt][2] = __expf(s[nt][2] - nm1);
            s[nt][3] = __expf(s[nt][3] - nm1);
            ps0 += s[nt][0] + s[nt][1];
            ps1 += s[nt][2] + s[nt][3];
        }
        ps0 += __shfl_xor_sync(0xffffffffu, ps0, 1);
        ps0 += __shfl_xor_sync(0xffffffffu, ps0, 2);
        ps1 += __shfl_xor_sync(0xffffffffu, ps1, 1);
        ps1 += __shfl_xor_sync(0xffffffffu, ps1, 2);

        l0 = l0 * f0 + ps0;  m0 = nm0;
        l1 = l1 * f1 + ps1;  m1 = nm1;

        #pragma unroll
        for (int nt = 0; nt < 8; nt++) {
            O[nt][0] *= f0; O[nt][1] *= f0;
            O[nt][2] *= f1; O[nt][3] *= f1;
        }

        // O += P V
        #pragma unroll
        for (int kc = 0; kc < 4; kc++) {
            uint32_t pa[4];
            pa[0] = packh2(s[2*kc  ][0], s[2*kc  ][1]);
            pa[1] = packh2(s[2*kc  ][2], s[2*kc  ][3]);
            pa[2] = packh2(s[2*kc+1][0], s[2*kc+1][1]);
            pa[3] = packh2(s[2*kc+1][2], s[2*kc+1][3]);

            uint32_t v4[4][4];
            #pragma unroll
            for (int p = 0; p < 4; p++)
                ldsm_x4_t(v4[p][0], v4[p][1], v4[p][2], v4[p][3],
                          vbs + (uint32_t)((kc*16 + vrow)*144 + (p*16 + vcol)*2));
            #pragma unroll
            for (int nt = 0; nt < 8; nt++)
                mma_f16(O[nt], pa, &v4[nt >> 1][(nt & 1) * 2]);
        }
    }

    // epilogue
    const float inv0 = 1.f / l0;
    const float inv1 = 1.f / l1;
    const size_t i0 = ((size_t)bb*SEQ + r0g)*EMBED + hh*HDIM;
    const size_t i1 = ((size_t)bb*SEQ + r1g)*EMBED + hh*HDIM;
    #pragma unroll
    for (int nt = 0; nt < 8; nt++) {
        const int c = nt*8 + (lane & 3)*2;
        *(uint32_t*)&g_C[i0 + c] = packh2(O[nt][0]*inv0, O[nt][1]*inv0);
        *(uint32_t*)&g_C[i1 + c] = packh2(O[nt][2]*inv1, O[nt][3]*inv1);
    }
}

// ---------------------------------------------------------------------------
extern "C" void kernel_launch(void* const* d_in, const int* in_sizes, int n_in,
                              void* d_out, int out_size)
{
    const float* x     = (const float*)d_in[0];   // [B,S,E]
    const float* w_qkv = (const float*)d_in[1];   // [3E,E]
    const float* b_qkv = (const float*)d_in[2];   // [3E]
    const float* w_out = (const float*)d_in[3];   // [E,E]
    const float* b_out = (const float*)d_in[4];   // [E]
    float* out = (float*)d_out;                   // [B,S,E]

    cudaFuncSetAttribute(attn_h, cudaFuncAttributeMaxDynamicSharedMemorySize,
                         ATTN_SMEM_BYTES);
    cudaFuncSetAttribute(gemm_h<0>, cudaFuncAttributeMaxDynamicSharedMemorySize,
                         GEMM_SMEM);
    cudaFuncSetAttribute(gemm_h<1>, cudaFuncAttributeMaxDynamicSharedMemorySize,
                         GEMM_SMEM);

    // 0. convert inputs/weights to fp16
    cvt_inputs<<<8192, 256>>>(x, w_qkv, w_out);

    // 1. QKV projection + head split (fp16 HMMA gemm, K-step 64)
    gemm_h<0><<<dim3((3*EMBED)/128, MROWS/128), 256, GEMM_SMEM>>>(
        b_qkv, nullptr, MROWS, 3*EMBED, EMBED);

    // 2. Causal flash attention (fp16, fp32 accum, pipelined K/V) -> fp16 ctx
    attn_h<<<dim3(SEQ/128, BATCH*NHEADS), 256, ATTN_SMEM_BYTES>>>();

    // 3. Output projection (fp16 HMMA gemm, K-step 64)
    gemm_h<1><<<dim3(EMBED/128, MROWS/128), 256, GEMM_SMEM>>>(
        b_out, out, MROWS, EMBED, EMBED);
}

// round 16
// speedup vs baseline: 1.1419x; 1.1419x over previous
#include <cuda_runtime.h>
#include <cuda_fp16.h>
#include <cstdint>

#define EMBED   1024
#define NHEADS  16
#define HDIM    64
#define BATCH   2
#define SEQ     2048
#define MROWS   (BATCH*SEQ)   // 4096

#define NEG_INF (-1e30f)

typedef __half fh;

// tcgen05 is NOT usable (harness emits compute_103 PTX; ptxas rejects it).
// All tensor work via mma.sync HMMA, fp16 operands + fp32 accumulators.
// rel_err ~5.2e-4 vs 1e-3 threshold — do not cut precision further.
// K-step 32 is the proven best (64 regressed: longer wait per group).

// ---------------------------------------------------------------------------
// Scratch (device globals). Everything single fp16.
// ---------------------------------------------------------------------------
__device__ fh g_X[(size_t)MROWS*EMBED];
__device__ fh g_Wq[(size_t)3*EMBED*EMBED];
__device__ fh g_Wo[(size_t)EMBED*EMBED];
__device__ fh g_Q[(size_t)MROWS*EMBED];
__device__ fh g_K[(size_t)MROWS*EMBED];
__device__ fh g_V[(size_t)MROWS*EMBED];
__device__ fh g_C[(size_t)MROWS*EMBED];

// ---------------------------------------------------------------------------
// PTX helpers
// ---------------------------------------------------------------------------
__device__ __forceinline__ uint32_t saddr(const void* p) {
    return (uint32_t)__cvta_generic_to_shared(p);
}
__device__ __forceinline__ void cpa16(uint32_t dst, const void* src) {
    asm volatile("cp.async.cg.shared.global [%0], [%1], 16;\n" :: "r"(dst), "l"(src));
}
__device__ __forceinline__ void cpa_commit() {
    asm volatile("cp.async.commit_group;\n");
}
template<int N>
__device__ __forceinline__ void cpa_wait() {
    asm volatile("cp.async.wait_group %0;\n" :: "n"(N));
}
__device__ __forceinline__ void ldsm_x4(uint32_t& r0, uint32_t& r1,
                                        uint32_t& r2, uint32_t& r3, uint32_t a) {
    asm volatile("ldmatrix.sync.aligned.m8n8.x4.shared.b16 {%0,%1,%2,%3}, [%4];"
                 : "=r"(r0), "=r"(r1), "=r"(r2), "=r"(r3) : "r"(a));
}
__device__ __forceinline__ void ldsm_x4_t(uint32_t& r0, uint32_t& r1,
                                          uint32_t& r2, uint32_t& r3, uint32_t a) {
    asm volatile("ldmatrix.sync.aligned.m8n8.x4.trans.shared.b16 {%0,%1,%2,%3}, [%4];"
                 : "=r"(r0), "=r"(r1), "=r"(r2), "=r"(r3) : "r"(a));
}
__device__ __forceinline__ void mma_f16(float* c, const uint32_t* a, const uint32_t* b) {
    asm volatile(
        "mma.sync.aligned.m16n8k16.row.col.f32.f16.f16.f32 "
        "{%0,%1,%2,%3}, {%4,%5,%6,%7}, {%8,%9}, {%0,%1,%2,%3};"
        : "+f"(c[0]), "+f"(c[1]), "+f"(c[2]), "+f"(c[3])
        : "r"(a[0]), "r"(a[1]), "r"(a[2]), "r"(a[3]), "r"(b[0]), "r"(b[1]));
}
__device__ __forceinline__ uint32_t packh2(float a, float b) {
    __half2 h = __floats2half2_rn(a, b);   // a -> low half
    return *(uint32_t*)&h;
}

// ---------------------------------------------------------------------------
// Input conversion pre-pass: x, w_qkv, w_out -> fp16 globals.
// ---------------------------------------------------------------------------
__global__ __launch_bounds__(256)
void cvt_inputs(const float* __restrict__ x, const float* __restrict__ wq,
                const float* __restrict__ wo)
{
    const int i = blockIdx.x * 256 + threadIdx.x;
    const float* src; fh* dst; int off;
    if (i < 1048576)            { src = x;  dst = g_X;  off = i; }
    else if (i < 1048576+786432){ src = wq; dst = g_Wq; off = i - 1048576; }
    else                        { src = wo; dst = g_Wo; off = i - 1835008; }
    float4 f = ((const float4*)src)[off];
    uint2 v; v.x = packh2(f.x, f.y); v.y = packh2(f.z, f.w);
    *(uint2*)(dst + (size_t)off*4) = v;
}

// ---------------------------------------------------------------------------
// Pipelined fp16 HMMA GEMM: out = A @ Bw^T + bias
// 256 threads, CTA tile 128x128, 8 warps (2m x 4n), warp tile 64x32.
// K-step 32. NEW: 3-stage cp.async pipeline, ONE __syncthreads per
// iteration (copy at iter ks targets stage (ks-1)%3, last read at iter
// ks-1 and protected by the leading sync — trailing sync removed).
// Stage: A 10240 B + B 10240 B = 20480; 3 stages = 61440 -> 2 CTAs/SM.
// ---------------------------------------------------------------------------
#define GSTAGE_B  20480
#define GEMM_SMEM (3*GSTAGE_B)   // 61440

template<int MODE>
__global__ __launch_bounds__(256, 2)
void gemm_h(const float* __restrict__ bias, float* __restrict__ C,
            int M, int N, int K)
{
    extern __shared__ fh sm[];
    const uint32_t smem0 = saddr(sm);

    const fh* Ap = (MODE == 0) ? g_X : g_C;
    const fh* Bp = (MODE == 0) ? g_Wq : g_Wo;

    const int tid  = threadIdx.x;
    const int lane = tid & 31;
    const int warp = tid >> 5;
    const int wm   = warp >> 2;
    const int wn   = warp & 3;
    const int bm   = blockIdx.y * 128;
    const int bn   = blockIdx.x * 128;

    const int lr    = tid >> 1;
    const int half_ = tid & 1;

    const fh* aP = Ap + (size_t)(bm + lr) * K + half_*16;
    const fh* bP = Bp + (size_t)(bn + lr) * K + half_*16;
    const uint32_t adst = smem0 + lr*80 + half_*32;
    const uint32_t bdst = adst + 10240;

    const int nsteps = K >> 5;

    auto copy_stage = [&](int k0, int stg) {
        const uint32_t d = stg * GSTAGE_B;
        cpa16(adst + d,      aP + k0);  cpa16(adst + d + 16, aP + k0 + 8);
        cpa16(bdst + d,      bP + k0);  cpa16(bdst + d + 16, bP + k0 + 8);
    };

    float acc[16][4];
    #pragma unroll
    for (int i = 0; i < 16; i++)
        #pragma unroll
        for (int j = 0; j < 4; j++) acc[i][j] = 0.f;

    const int arow = wm*64 + (lane & 15);
    const int acol = ((lane >> 4) & 1) * 8;
    const int brow = wn*32 + (lane & 7) + ((lane >> 4) & 1) * 8;
    const int bcol = ((lane >> 3) & 1) * 8;
    const uint32_t aoff = (uint32_t)(arow*80 + acol*2);
    const uint32_t boff = (uint32_t)(10240 + brow*80 + bcol*2);

    // prologue: 2 tiles in flight
    copy_stage(0, 0);   cpa_commit();
    copy_stage(32, 1);  cpa_commit();

    for (int ks = 0; ks < nsteps; ks++) {
        cpa_wait<1>();       // tile ks complete (tile ks+1 may be in flight)
        __syncthreads();     // all warps aligned; stage (ks-1)%3 reads done

        const int nk = ks + 2;
        if (nk < nsteps) copy_stage(nk*32, nk % 3);
        cpa_commit();

        const uint32_t base = smem0 + (ks % 3) * GSTAGE_B;

        #pragma unroll
        for (int kk = 0; kk < 2; kk++) {
            const uint32_t ab  = base + aoff + kk*32;
            const uint32_t bbx = base + boff + kk*32;
            uint32_t bh[2][4];
            #pragma unroll
            for (int p = 0; p < 2; p++)
                ldsm_x4(bh[p][0], bh[p][1], bh[p][2], bh[p][3], bbx + p*1280);
            #pragma unroll
            for (int t = 0; t < 4; t++) {
                uint32_t ah[4];
                ldsm_x4(ah[0], ah[1], ah[2], ah[3], ab + t*1280);
                #pragma unroll
                for (int n = 0; n < 4; n++)
                    mma_f16(acc[t*4 + n], ah, &bh[n >> 1][(n & 1) * 2]);
            }
        }
    }

    // epilogue
    #pragma unroll
    for (int t = 0; t < 4; t++) {
        const int r0 = bm + wm*64 + t*16 + (lane >> 2);
        #pragma unroll
        for (int n = 0; n < 4; n++) {
            const int col = bn + wn*32 + n*8 + (lane & 3)*2;
            const float b0v = bias[col], b1v = bias[col + 1];
            const float* c = acc[t*4 + n];
            if (MODE == 0) {
                const int sel = col >> 10;      // 0=Q 1=K 2=V
                const int e   = col & 1023;
                fh* pq = (sel == 0) ? g_Q : (sel == 1) ? g_K : g_V;
                const int hh = e >> 6, dd = e & 63;
                #pragma unroll
                for (int rr = 0; rr < 2; rr++) {
                    const int row = r0 + rr*8;
                    const int bbv = row >> 11, ss = row & 2047;
                    const size_t idx = (((size_t)(bbv*NHEADS + hh))*SEQ + ss)*HDIM + dd;
                    *(uint32_t*)&pq[idx] = packh2(c[rr*2] + b0v, c[rr*2+1] + b1v);
                }
            } else {
                float2 v0; v0.x = c[0] + b0v; v0.y = c[1] + b1v;
                float2 v1; v1.x = c[2] + b0v; v1.y = c[3] + b1v;
                *(float2*)&C[(size_t)r0       * N + col] = v0;
                *(float2*)&C[(size_t)(r0 + 8) * N + col] = v1;
            }
        }
    }
}

// ---------------------------------------------------------------------------
// fp16 flash attention (causal), fp32 accumulators.
// NEW: 3-stage K/V cp.async pipeline, one __syncthreads per k-tile
// (same proof as the gemm: copy targets the stage read two iterations ago).
// smem (halves): Q[128][72] @0 (9216), K stages @9216+stg*4608,
// V stages @23040+stg*4608. Total 36864 halves = 73728 B.
// ---------------------------------------------------------------------------
#define ATTN_SMEM_BYTES 73728

__global__ __launch_bounds__(256, 1)
void attn_h()
{
    extern __shared__ fh sb[];
    fh (*Qs)[72] = (fh(*)[72])(sb);

    const int qt   = (int)(gridDim.x - 1) - (int)blockIdx.x;   // big tiles first
    const int bhid = blockIdx.y;
    const int bb   = bhid / NHEADS;
    const int hh   = bhid % NHEADS;

    const size_t hb = (size_t)bhid * SEQ * HDIM;

    const int tid  = threadIdx.x;
    const int lane = tid & 31;
    const int w    = tid >> 5;
    const int qbase = qt * 128;

    const int kr = tid >> 2, q4 = tid & 3;

    auto load_kv = [&](int kt, int stg) {
        const size_t srcoff = hb + (size_t)(kt*64 + kr)*HDIM + q4*16;
        const uint32_t doff = (uint32_t)(stg*9216 + kr*144 + q4*32);
        const uint32_t dk = saddr(sb + 9216)  + doff;
        const uint32_t dv = saddr(sb + 23040) + doff;
        cpa16(dk, g_K + srcoff);  cpa16(dk + 16, g_K + srcoff + 8);
        cpa16(dv, g_V + srcoff);  cpa16(dv + 16, g_V + srcoff + 8);
    };

    const int nktiles = 2*qt + 2;   // >= 2 always

    // prologue: Q group, then KV tiles 0 and 1
    {
        const int lr = tid >> 1, hx = tid & 1;
        const fh* qsrc = g_Q + hb + (size_t)(qbase + lr)*HDIM + hx*32;
        const uint32_t dq = saddr(&Qs[lr][hx*32]);
        #pragma unroll
        for (int u = 0; u < 4; u++)
            cpa16(dq + u*16, qsrc + u*8);
        cpa_commit();                 // group 1: Q
    }
    load_kv(0, 0);  cpa_commit();     // group 2: KV tile 0
    load_kv(1, 1);  cpa_commit();     // group 3: KV tile 1
    cpa_wait<2>();                    // Q complete
    __syncthreads();

    uint32_t qf[4][4];
    {
        const int arow = w*16 + (lane & 15);
        const int acol = ((lane >> 4) & 1) * 8;
        #pragma unroll
        for (int kc = 0; kc < 4; kc++)
            ldsm_x4(qf[kc][0], qf[kc][1], qf[kc][2], qf[kc][3],
                    saddr(&Qs[arow][kc*16 + acol]));
    }

    float O[8][4];
    #pragma unroll
    for (int nt = 0; nt < 8; nt++)
        #pragma unroll
        for (int e = 0; e < 4; e++) O[nt][e] = 0.f;

    float m0 = NEG_INF, m1 = NEG_INF, l0 = 0.f, l1 = 0.f;
    const int r0g = qbase + w*16 + (lane >> 2);
    const int r1g = r0g + 8;
    const int wr  = qbase + w*16;

    const int krow = (lane & 7) + ((lane >> 4) & 1) * 8;
    const int kcol = ((lane >> 3) & 1) * 8;
    const int vrow = (lane & 7) + ((lane >> 3) & 1) * 8;
    const int vcol = ((lane >> 4) & 1) * 8;

    for (int kt = 0; kt < nktiles; kt++) {
        const int kbase = kt * 64;
        cpa_wait<1>();     // KV tile kt complete (kt+1 may be in flight)
        __syncthreads();   // stage (kt-1)%3 reads finished everywhere

        const int nk = kt + 2;
        if (nk < nktiles) load_kv(nk, nk % 3);
        cpa_commit();

        if (wr + 15 < kbase) continue;   // warp fully masked for this tile

        const uint32_t kbs = saddr(sb + 9216)  + (kt % 3)*9216;
        const uint32_t vbs = saddr(sb + 23040) + (kt % 3)*9216;

        // S = Q K^T
        float s[8][4];
        #pragma unroll
        for (int nt = 0; nt < 8; nt++)
            #pragma unroll
            for (int e = 0; e < 4; e++) s[nt][e] = 0.f;

        #pragma unroll
        for (int kc = 0; kc < 4; kc++) {
            uint32_t k4[4][4];
            #pragma unroll
            for (int p = 0; p < 4; p++)
                ldsm_x4(k4[p][0], k4[p][1], k4[p][2], k4[p][3],
                        kbs + (uint32_t)((p*16 + krow)*144 + (kc*16 + kcol)*2));
            #pragma unroll
            for (int nt = 0; nt < 8; nt++)
                mma_f16(s[nt], qf[kc], &k4[nt >> 1][(nt & 1) * 2]);
        }

        #pragma unroll
        for (int nt = 0; nt < 8; nt++)
            #pragma unroll
            for (int e = 0; e < 4; e++) s[nt][e] *= 0.125f;

        if (kbase + 63 > wr) {
            #pragma unroll
            for (int nt = 0; nt < 8; nt++) {
                const int c0 = kbase + nt*8 + ((lane & 3) << 1);
                if (c0     > r0g) s[nt][0] = NEG_INF;
                if (c0 + 1 > r0g) s[nt][1] = NEG_INF;
                if (c0     > r1g) s[nt][2] = NEG_INF;
                if (c0 + 1 > r1g) s[nt][3] = NEG_INF;
            }
        }

        // online softmax
        float mx0 = NEG_INF, mx1 = NEG_INF;
        #pragma unroll
        for (int nt = 0; nt < 8; nt++) {
            mx0 = fmaxf(mx0, fmaxf(s[nt][0], s[nt][1]));
            mx1 = fmaxf(mx1, fmaxf(s[nt][2], s[nt][3]));
        }
        mx0 = fmaxf(mx0, __shfl_xor_sync(0xffffffffu, mx0, 1));
        mx0 = fmaxf(mx0, __shfl_xor_sync(0xffffffffu, mx0, 2));
        mx1 = fmaxf(mx1, __shfl_xor_sync(0xffffffffu, mx1, 1));
        mx1 = fmaxf(mx1, __shfl_xor_sync(0xffffffffu, mx1, 2));

        const float nm0 = fmaxf(m0, mx0);
        const float nm1 = fmaxf(m1, mx1);
        const float f0 = __expf(m0 - nm0);
        const float f1 = __expf(m1 - nm1);

        float ps0 = 0.f, ps1 = 0.f;
        #pragma unroll
        for (int nt = 0; nt < 8; nt++) {
            s[nt][0] = __expf(s[nt][0] - nm0);
            s[nt][1] = __expf(s[nt][1] - nm0);
            s[nt][2] = __expf(s[nt][2] - nm1);
            s[nt][3] = __expf(s[nt][3] - nm1);
            ps0 += s[nt][0] + s[nt][1];
            ps1 += s[nt][2] + s[nt][3];
        }
        ps0 += __shfl_xor_sync(0xffffffffu, ps0, 1);
        ps0 += __shfl_xor_sync(0xffffffffu, ps0, 2);
        ps1 += __shfl_xor_sync(0xffffffffu, ps1, 1);
        ps1 += __shfl_xor_sync(0xffffffffu, ps1, 2);

        l0 = l0 * f0 + ps0;  m0 = nm0;
        l1 = l1 * f1 + ps1;  m1 = nm1;

        #pragma unroll
        for (int nt = 0; nt < 8; nt++) {
            O[nt][0] *= f0; O[nt][1] *= f0;
            O[nt][2] *= f1; O[nt][3] *= f1;
        }

        // O += P V
        #pragma unroll
        for (int kc = 0; kc < 4; kc++) {
            uint32_t pa[4];
            pa[0] = packh2(s[2*kc  ][0], s[2*kc  ][1]);
            pa[1] = packh2(s[2*kc  ][2], s[2*kc  ][3]);
            pa[2] = packh2(s[2*kc+1][0], s[2*kc+1][1]);
            pa[3] = packh2(s[2*kc+1][2], s[2*kc+1][3]);

            uint32_t v4[4][4];
            #pragma unroll
            for (int p = 0; p < 4; p++)
                ldsm_x4_t(v4[p][0], v4[p][1], v4[p][2], v4[p][3],
                          vbs + (uint32_t)((kc*16 + vrow)*144 + (p*16 + vcol)*2));
            #pragma unroll
            for (int nt = 0; nt < 8; nt++)
                mma_f16(O[nt], pa, &v4[nt >> 1][(nt & 1) * 2]);
        }
    }

    // epilogue
    const float inv0 = 1.f / l0;
    const float inv1 = 1.f / l1;
    const size_t i0 = ((size_t)bb*SEQ + r0g)*EMBED + hh*HDIM;
    const size_t i1 = ((size_t)bb*SEQ + r1g)*EMBED + hh*HDIM;
    #pragma unroll
    for (int nt = 0; nt < 8; nt++) {
        const int c = nt*8 + (lane & 3)*2;
        *(uint32_t*)&g_C[i0 + c] = packh2(O[nt][0]*inv0, O[nt][1]*inv0);
        *(uint32_t*)&g_C[i1 + c] = packh2(O[nt][2]*inv1, O[nt][3]*inv1);
    }
}

// ---------------------------------------------------------------------------
extern "C" void kernel_launch(void* const* d_in, const int* in_sizes, int n_in,
                              void* d_out, int out_size)
{
    const float* x     = (const float*)d_in[0];   // [B,S,E]
    const float* w_qkv = (const float*)d_in[1];   // [3E,E]
    const float* b_qkv = (const float*)d_in[2];   // [3E]
    const float* w_out = (const float*)d_in[3];   // [E,E]
    const float* b_out = (const float*)d_in[4];   // [E]
    float* out = (float*)d_out;                   // [B,S,E]

    cudaFuncSetAttribute(attn_h, cudaFuncAttributeMaxDynamicSharedMemorySize,
                         ATTN_SMEM_BYTES);
    cudaFuncSetAttribute(gemm_h<0>, cudaFuncAttributeMaxDynamicSharedMemorySize,
                         GEMM_SMEM);
    cudaFuncSetAttribute(gemm_h<1>, cudaFuncAttributeMaxDynamicSharedMemorySize,
                         GEMM_SMEM);

    // 0. convert inputs/weights to fp16
    cvt_inputs<<<8192, 256>>>(x, w_qkv, w_out);

    // 1. QKV projection + head split (fp16 HMMA, 3-stage/1-sync pipeline)
    gemm_h<0><<<dim3((3*EMBED)/128, MROWS/128), 256, GEMM_SMEM>>>(
        b_qkv, nullptr, MROWS, 3*EMBED, EMBED);

    // 2. Causal flash attention (fp16, fp32 accum, 3-stage K/V) -> fp16 ctx
    attn_h<<<dim3(SEQ/128, BATCH*NHEADS), 256, ATTN_SMEM_BYTES>>>();

    // 3. Output projection (fp16 HMMA, 3-stage/1-sync pipeline)
    gemm_h<1><<<dim3(EMBED/128, MROWS/128), 256, GEMM_SMEM>>>(
        b_out, out, MROWS, EMBED, EMBED);
}

// round 17
// speedup vs baseline: 1.1979x; 1.0491x over previous
#include <cuda_runtime.h>
#include <cuda_fp16.h>
#include <cstdint>

#define EMBED   1024
#define NHEADS  16
#define HDIM    64
#define BATCH   2
#define SEQ     2048
#define MROWS   (BATCH*SEQ)   // 4096

#define NEG_INF (-1e30f)
// 1/sqrt(64) * log2(e): folded into Q at the QKV epilogue; attention softmax
// then runs in base-2 (exp2f) with no per-tile scale loop.
#define QSCALE  0.18033688011112042f

typedef __half fh;

// tcgen05 is NOT usable (harness emits compute_103 PTX; ptxas rejects it).
// All tensor work via mma.sync HMMA, fp16 operands + fp32 accumulators.
// rel_err ~5.2e-4 vs 1e-3 threshold — do not cut precision further.
// K-step 32 + 3-stage/1-sync pipeline is the proven best gemm config.

// ---------------------------------------------------------------------------
// Scratch (device globals). Everything single fp16.
// ---------------------------------------------------------------------------
__device__ fh g_X[(size_t)MROWS*EMBED];
__device__ fh g_Wq[(size_t)3*EMBED*EMBED];
__device__ fh g_Wo[(size_t)EMBED*EMBED];
__device__ fh g_Q[(size_t)MROWS*EMBED];
__device__ fh g_K[(size_t)MROWS*EMBED];
__device__ fh g_V[(size_t)MROWS*EMBED];
__device__ fh g_C[(size_t)MROWS*EMBED];

// ---------------------------------------------------------------------------
// PTX helpers
// ---------------------------------------------------------------------------
__device__ __forceinline__ uint32_t saddr(const void* p) {
    return (uint32_t)__cvta_generic_to_shared(p);
}
__device__ __forceinline__ void cpa16(uint32_t dst, const void* src) {
    asm volatile("cp.async.cg.shared.global [%0], [%1], 16;\n" :: "r"(dst), "l"(src));
}
__device__ __forceinline__ void cpa_commit() {
    asm volatile("cp.async.commit_group;\n");
}
template<int N>
__device__ __forceinline__ void cpa_wait() {
    asm volatile("cp.async.wait_group %0;\n" :: "n"(N));
}
__device__ __forceinline__ void ldsm_x4(uint32_t& r0, uint32_t& r1,
                                        uint32_t& r2, uint32_t& r3, uint32_t a) {
    asm volatile("ldmatrix.sync.aligned.m8n8.x4.shared.b16 {%0,%1,%2,%3}, [%4];"
                 : "=r"(r0), "=r"(r1), "=r"(r2), "=r"(r3) : "r"(a));
}
__device__ __forceinline__ void ldsm_x4_t(uint32_t& r0, uint32_t& r1,
                                          uint32_t& r2, uint32_t& r3, uint32_t a) {
    asm volatile("ldmatrix.sync.aligned.m8n8.x4.trans.shared.b16 {%0,%1,%2,%3}, [%4];"
                 : "=r"(r0), "=r"(r1), "=r"(r2), "=r"(r3) : "r"(a));
}
__device__ __forceinline__ void mma_f16(float* c, const uint32_t* a, const uint32_t* b) {
    asm volatile(
        "mma.sync.aligned.m16n8k16.row.col.f32.f16.f16.f32 "
        "{%0,%1,%2,%3}, {%4,%5,%6,%7}, {%8,%9}, {%0,%1,%2,%3};"
        : "+f"(c[0]), "+f"(c[1]), "+f"(c[2]), "+f"(c[3])
        : "r"(a[0]), "r"(a[1]), "r"(a[2]), "r"(a[3]), "r"(b[0]), "r"(b[1]));
}
__device__ __forceinline__ uint32_t packh2(float a, float b) {
    __half2 h = __floats2half2_rn(a, b);   // a -> low half
    return *(uint32_t*)&h;
}

// ---------------------------------------------------------------------------
// Input conversion pre-pass: x, w_qkv, w_out -> fp16 globals.
// ---------------------------------------------------------------------------
__global__ __launch_bounds__(256)
void cvt_inputs(const float* __restrict__ x, const float* __restrict__ wq,
                const float* __restrict__ wo)
{
    const int i = blockIdx.x * 256 + threadIdx.x;
    const float* src; fh* dst; int off;
    if (i < 1048576)            { src = x;  dst = g_X;  off = i; }
    else if (i < 1048576+786432){ src = wq; dst = g_Wq; off = i - 1048576; }
    else                        { src = wo; dst = g_Wo; off = i - 1835008; }
    float4 f = ((const float4*)src)[off];
    uint2 v; v.x = packh2(f.x, f.y); v.y = packh2(f.z, f.w);
    *(uint2*)(dst + (size_t)off*4) = v;
}

// ---------------------------------------------------------------------------
// Pipelined fp16 HMMA GEMM: out = A @ Bw^T + bias
// 256 threads, CTA tile 128x128, 8 warps (2m x 4n), warp tile 64x32.
// K-step 32, 3-stage cp.async pipeline, ONE __syncthreads per iteration.
// Stage: A 10240 B + B 10240 B = 20480; 3 stages = 61440 -> 2 CTAs/SM.
// MODE 0 epilogue scatters fp16 Q/K/V; Q pre-scaled by QSCALE.
// ---------------------------------------------------------------------------
#define GSTAGE_B  20480
#define GEMM_SMEM (3*GSTAGE_B)   // 61440

template<int MODE>
__global__ __launch_bounds__(256, 2)
void gemm_h(const float* __restrict__ bias, float* __restrict__ C,
            int M, int N, int K)
{
    extern __shared__ fh sm[];
    const uint32_t smem0 = saddr(sm);

    const fh* Ap = (MODE == 0) ? g_X : g_C;
    const fh* Bp = (MODE == 0) ? g_Wq : g_Wo;

    const int tid  = threadIdx.x;
    const int lane = tid & 31;
    const int warp = tid >> 5;
    const int wm   = warp >> 2;
    const int wn   = warp & 3;
    const int bm   = blockIdx.y * 128;
    const int bn   = blockIdx.x * 128;

    const int lr    = tid >> 1;
    const int half_ = tid & 1;

    const fh* aP = Ap + (size_t)(bm + lr) * K + half_*16;
    const fh* bP = Bp + (size_t)(bn + lr) * K + half_*16;
    const uint32_t adst = smem0 + lr*80 + half_*32;
    const uint32_t bdst = adst + 10240;

    const int nsteps = K >> 5;

    auto copy_stage = [&](int k0, int stg) {
        const uint32_t d = stg * GSTAGE_B;
        cpa16(adst + d,      aP + k0);  cpa16(adst + d + 16, aP + k0 + 8);
        cpa16(bdst + d,      bP + k0);  cpa16(bdst + d + 16, bP + k0 + 8);
    };

    float acc[16][4];
    #pragma unroll
    for (int i = 0; i < 16; i++)
        #pragma unroll
        for (int j = 0; j < 4; j++) acc[i][j] = 0.f;

    const int arow = wm*64 + (lane & 15);
    const int acol = ((lane >> 4) & 1) * 8;
    const int brow = wn*32 + (lane & 7) + ((lane >> 4) & 1) * 8;
    const int bcol = ((lane >> 3) & 1) * 8;
    const uint32_t aoff = (uint32_t)(arow*80 + acol*2);
    const uint32_t boff = (uint32_t)(10240 + brow*80 + bcol*2);

    // prologue: 2 tiles in flight
    copy_stage(0, 0);   cpa_commit();
    copy_stage(32, 1);  cpa_commit();

    for (int ks = 0; ks < nsteps; ks++) {
        cpa_wait<1>();       // tile ks complete (tile ks+1 may be in flight)
        __syncthreads();     // all warps aligned; stage (ks-1)%3 reads done

        const int nk = ks + 2;
        if (nk < nsteps) copy_stage(nk*32, nk % 3);
        cpa_commit();

        const uint32_t base = smem0 + (ks % 3) * GSTAGE_B;

        #pragma unroll
        for (int kk = 0; kk < 2; kk++) {
            const uint32_t ab  = base + aoff + kk*32;
            const uint32_t bbx = base + boff + kk*32;
            uint32_t bh[2][4];
            #pragma unroll
            for (int p = 0; p < 2; p++)
                ldsm_x4(bh[p][0], bh[p][1], bh[p][2], bh[p][3], bbx + p*1280);
            #pragma unroll
            for (int t = 0; t < 4; t++) {
                uint32_t ah[4];
                ldsm_x4(ah[0], ah[1], ah[2], ah[3], ab + t*1280);
                #pragma unroll
                for (int n = 0; n < 4; n++)
                    mma_f16(acc[t*4 + n], ah, &bh[n >> 1][(n & 1) * 2]);
            }
        }
    }

    // epilogue
    #pragma unroll
    for (int t = 0; t < 4; t++) {
        const int r0 = bm + wm*64 + t*16 + (lane >> 2);
        #pragma unroll
        for (int n = 0; n < 4; n++) {
            const int col = bn + wn*32 + n*8 + (lane & 3)*2;
            const float b0v = bias[col], b1v = bias[col + 1];
            const float* c = acc[t*4 + n];
            if (MODE == 0) {
                const int sel = col >> 10;      // 0=Q 1=K 2=V
                const int e   = col & 1023;
                fh* pq = (sel == 0) ? g_Q : (sel == 1) ? g_K : g_V;
                const float sc = (sel == 0) ? QSCALE : 1.f;
                const int hh = e >> 6, dd = e & 63;
                #pragma unroll
                for (int rr = 0; rr < 2; rr++) {
                    const int row = r0 + rr*8;
                    const int bbv = row >> 11, ss = row & 2047;
                    const size_t idx = (((size_t)(bbv*NHEADS + hh))*SEQ + ss)*HDIM + dd;
                    *(uint32_t*)&pq[idx] = packh2((c[rr*2]   + b0v) * sc,
                                                  (c[rr*2+1] + b1v) * sc);
                }
            } else {
                float2 v0; v0.x = c[0] + b0v; v0.y = c[1] + b1v;
                float2 v1; v1.x = c[2] + b0v; v1.y = c[3] + b1v;
                *(float2*)&C[(size_t)r0       * N + col] = v0;
                *(float2*)&C[(size_t)(r0 + 8) * N + col] = v1;
            }
        }
    }
}

// ---------------------------------------------------------------------------
// fp16 flash attention (causal), fp32 accumulators.
// 3-stage K/V cp.async pipeline, one __syncthreads per k-tile.
// NEW: 2 CTAs/SM (launch_bounds(256,2)) — 16 warps/SM hide softmax stalls.
// NEW: base-2 softmax (Q pre-scaled by 1/sqrt(d)*log2e); no scale loop.
// smem (halves): Q[128][72] @0 (9216), K stages @9216+stg*4608,
// V stages @23040+stg*4608. Total 36864 halves = 73728 B (2 CTAs = 147456).
// ---------------------------------------------------------------------------
#define ATTN_SMEM_BYTES 73728

__global__ __launch_bounds__(256, 2)
void attn_h()
{
    extern __shared__ fh sb[];
    fh (*Qs)[72] = (fh(*)[72])(sb);

    const int qt   = (int)(gridDim.x - 1) - (int)blockIdx.x;   // big tiles first
    const int bhid = blockIdx.y;
    const int bb   = bhid / NHEADS;
    const int hh   = bhid % NHEADS;

    const size_t hb = (size_t)bhid * SEQ * HDIM;

    const int tid  = threadIdx.x;
    const int lane = tid & 31;
    const int w    = tid >> 5;
    const int qbase = qt * 128;

    const int kr = tid >> 2, q4 = tid & 3;

    auto load_kv = [&](int kt, int stg) {
        const size_t srcoff = hb + (size_t)(kt*64 + kr)*HDIM + q4*16;
        const uint32_t doff = (uint32_t)(stg*9216 + kr*144 + q4*32);
        const uint32_t dk = saddr(sb + 9216)  + doff;
        const uint32_t dv = saddr(sb + 23040) + doff;
        cpa16(dk, g_K + srcoff);  cpa16(dk + 16, g_K + srcoff + 8);
        cpa16(dv, g_V + srcoff);  cpa16(dv + 16, g_V + srcoff + 8);
    };

    const int nktiles = 2*qt + 2;   // >= 2 always

    // prologue: Q group, then KV tiles 0 and 1
    {
        const int lr = tid >> 1, hx = tid & 1;
        const fh* qsrc = g_Q + hb + (size_t)(qbase + lr)*HDIM + hx*32;
        const uint32_t dq = saddr(&Qs[lr][hx*32]);
        #pragma unroll
        for (int u = 0; u < 4; u++)
            cpa16(dq + u*16, qsrc + u*8);
        cpa_commit();                 // group 1: Q
    }
    load_kv(0, 0);  cpa_commit();     // group 2: KV tile 0
    load_kv(1, 1);  cpa_commit();     // group 3: KV tile 1
    cpa_wait<2>();                    // Q complete
    __syncthreads();

    uint32_t qf[4][4];
    {
        const int arow = w*16 + (lane & 15);
        const int acol = ((lane >> 4) & 1) * 8;
        #pragma unroll
        for (int kc = 0; kc < 4; kc++)
            ldsm_x4(qf[kc][0], qf[kc][1], qf[kc][2], qf[kc][3],
                    saddr(&Qs[arow][kc*16 + acol]));
    }

    float O[8][4];
    #pragma unroll
    for (int nt = 0; nt < 8; nt++)
        #pragma unroll
        for (int e = 0; e < 4; e++) O[nt][e] = 0.f;

    float m0 = NEG_INF, m1 = NEG_INF, l0 = 0.f, l1 = 0.f;
    const int r0g = qbase + w*16 + (lane >> 2);
    const int r1g = r0g + 8;
    const int wr  = qbase + w*16;

    const int krow = (lane & 7) + ((lane >> 4) & 1) * 8;
    const int kcol = ((lane >> 3) & 1) * 8;
    const int vrow = (lane & 7) + ((lane >> 3) & 1) * 8;
    const int vcol = ((lane >> 4) & 1) * 8;

    for (int kt = 0; kt < nktiles; kt++) {
        const int kbase = kt * 64;
        cpa_wait<1>();     // KV tile kt complete (kt+1 may be in flight)
        __syncthreads();   // stage (kt-1)%3 reads finished everywhere

        const int nk = kt + 2;
        if (nk < nktiles) load_kv(nk, nk % 3);
        cpa_commit();

        if (wr + 15 < kbase) continue;   // warp fully masked for this tile

        const uint32_t kbs = saddr(sb + 9216)  + (kt % 3)*9216;
        const uint32_t vbs = saddr(sb + 23040) + (kt % 3)*9216;

        // S = Q K^T  (already in base-2 log domain via QSCALE)
        float s[8][4];
        #pragma unroll
        for (int nt = 0; nt < 8; nt++)
            #pragma unroll
            for (int e = 0; e < 4; e++) s[nt][e] = 0.f;

        #pragma unroll
        for (int kc = 0; kc < 4; kc++) {
            uint32_t k4[4][4];
            #pragma unroll
            for (int p = 0; p < 4; p++)
                ldsm_x4(k4[p][0], k4[p][1], k4[p][2], k4[p][3],
                        kbs + (uint32_t)((p*16 + krow)*144 + (kc*16 + kcol)*2));
            #pragma unroll
            for (int nt = 0; nt < 8; nt++)
                mma_f16(s[nt], qf[kc], &k4[nt >> 1][(nt & 1) * 2]);
        }

        if (kbase + 63 > wr) {
            #pragma unroll
            for (int nt = 0; nt < 8; nt++) {
                const int c0 = kbase + nt*8 + ((lane & 3) << 1);
                if (c0     > r0g) s[nt][0] = NEG_INF;
                if (c0 + 1 > r0g) s[nt][1] = NEG_INF;
                if (c0     > r1g) s[nt][2] = NEG_INF;
                if (c0 + 1 > r1g) s[nt][3] = NEG_INF;
            }
        }

        // online softmax (base 2)
        float mx0 = NEG_INF, mx1 = NEG_INF;
        #pragma unroll
        for (int nt = 0; nt < 8; nt++) {
            mx0 = fmaxf(mx0, fmaxf(s[nt][0], s[nt][1]));
            mx1 = fmaxf(mx1, fmaxf(s[nt][2], s[nt][3]));
        }
        mx0 = fmaxf(mx0, __shfl_xor_sync(0xffffffffu, mx0, 1));
        mx0 = fmaxf(mx0, __shfl_xor_sync(0xffffffffu, mx0, 2));
        mx1 = fmaxf(mx1, __shfl_xor_sync(0xffffffffu, mx1, 1));
        mx1 = fmaxf(mx1, __shfl_xor_sync(0xffffffffu, mx1, 2));

        const float nm0 = fmaxf(m0, mx0);
        const float nm1 = fmaxf(m1, mx1);
        const float f0 = exp2f(m0 - nm0);
        const float f1 = exp2f(m1 - nm1);

        float ps0 = 0.f, ps1 = 0.f;
        #pragma unroll
        for (int nt = 0; nt < 8; nt++) {
            s[nt][0] = exp2f(s[nt][0] - nm0);
            s[nt][1] = exp2f(s[nt][1] - nm0);
            s[nt][2] = exp2f(s[nt][2] - nm1);
            s[nt][3] = exp2f(s[nt][3] - nm1);
            ps0 += s[nt][0] + s[nt][1];
            ps1 += s[nt][2] + s[nt][3];
        }
        ps0 += __shfl_xor_sync(0xffffffffu, ps0, 1);
        ps0 += __shfl_xor_sync(0xffffffffu, ps0, 2);
        ps1 += __shfl_xor_sync(0xffffffffu, ps1, 1);
        ps1 += __shfl_xor_sync(0xffffffffu, ps1, 2);

        l0 = l0 * f0 + ps0;  m0 = nm0;
        l1 = l1 * f1 + ps1;  m1 = nm1;

        #pragma unroll
        for (int nt = 0; nt < 8; nt++) {
            O[nt][0] *= f0; O[nt][1] *= f0;
            O[nt][2] *= f1; O[nt][3] *= f1;
        }

        // O += P V
        #pragma unroll
        for (int kc = 0; kc < 4; kc++) {
            uint32_t pa[4];
            pa[0] = packh2(s[2*kc  ][0], s[2*kc  ][1]);
            pa[1] = packh2(s[2*kc  ][2], s[2*kc  ][3]);
            pa[2] = packh2(s[2*kc+1][0], s[2*kc+1][1]);
            pa[3] = packh2(s[2*kc+1][2], s[2*kc+1][3]);

            uint32_t v4[4][4];
            #pragma unroll
            for (int p = 0; p < 4; p++)
                ldsm_x4_t(v4[p][0], v4[p][1], v4[p][2], v4[p][3],
                          vbs + (uint32_t)((kc*16 + vrow)*144 + (p*16 + vcol)*2));
            #pragma unroll
            for (int nt = 0; nt < 8; nt++)
                mma_f16(O[nt], pa, &v4[nt >> 1][(nt & 1) * 2]);
        }
    }

    // epilogue
    const float inv0 = 1.f / l0;
    const float inv1 = 1.f / l1;
    const size_t i0 = ((size_t)bb*SEQ + r0g)*EMBED + hh*HDIM;
    const size_t i1 = ((size_t)bb*SEQ + r1g)*EMBED + hh*HDIM;
    #pragma unroll
    for (int nt = 0; nt < 8; nt++) {
        const int c = nt*8 + (lane & 3)*2;
        *(uint32_t*)&g_C[i0 + c] = packh2(O[nt][0]*inv0, O[nt][1]*inv0);
        *(uint32_t*)&g_C[i1 + c] = packh2(O[nt][2]*inv1, O[nt][3]*inv1);
    }
}

// ---------------------------------------------------------------------------
extern "C" void kernel_launch(void* const* d_in, const int* in_sizes, int n_in,
                              void* d_out, int out_size)
{
    const float* x     = (const float*)d_in[0];   // [B,S,E]
    const float* w_qkv = (const float*)d_in[1];   // [3E,E]
    const float* b_qkv = (const float*)d_in[2];   // [3E]
    const float* w_out = (const float*)d_in[3];   // [E,E]
    const float* b_out = (const float*)d_in[4];   // [E]
    float* out = (float*)d_out;                   // [B,S,E]

    cudaFuncSetAttribute(attn_h, cudaFuncAttributeMaxDynamicSharedMemorySize,
                         ATTN_SMEM_BYTES);
    cudaFuncSetAttribute(gemm_h<0>, cudaFuncAttributeMaxDynamicSharedMemorySize,
                         GEMM_SMEM);
    cudaFuncSetAttribute(gemm_h<1>, cudaFuncAttributeMaxDynamicSharedMemorySize,
                         GEMM_SMEM);

    // 0. convert inputs/weights to fp16
    cvt_inputs<<<8192, 256>>>(x, w_qkv, w_out);

    // 1. QKV projection + head split (Q pre-scaled by 1/sqrt(d)*log2e)
    gemm_h<0><<<dim3((3*EMBED)/128, MROWS/128), 256, GEMM_SMEM>>>(
        b_qkv, nullptr, MROWS, 3*EMBED, EMBED);

    // 2. Causal flash attention (fp16, base-2 softmax, 2 CTAs/SM) -> fp16 ctx
    attn_h<<<dim3(SEQ/128, BATCH*NHEADS), 256, ATTN_SMEM_BYTES>>>();

    // 3. Output projection
    gemm_h<1><<<dim3(EMBED/128, MROWS/128), 256, GEMM_SMEM>>>(
        b_out, out, MROWS, EMBED, EMBED);
}